// round 4
// baseline (speedup 1.0000x reference)
#include <cuda_runtime.h>
#include <cuda_fp16.h>
#include <math.h>
#include <stdint.h>

#define BB 2
#define SS 8500
#define CC 512
#define HH 8
#define DD 64
#define DFFN 1024
#define MT (BB*SS)   // 17000

#define PA 36
#define PB 136
#define ABUF (128*PA)
#define BBUF (32*PB)
#define SMEM_FLOATS (2*ABUF + 2*BBUF)

// ---------------- scratch ------------------------------------------------------
__device__ float  g_q   [MT*CC];
__device__ __half g_valh[MT*CC];
__device__ float  g_off [MT*256];
__device__ float  g_lgt [MT*128];
__device__ float  g_smp [MT*CC];
__device__ float  g_tmp [MT*CC];
__device__ float  g_x   [MT*CC];
__device__ float  g_hid [MT*DFFN];

__device__ __forceinline__ uint32_t smem_u32(const void* p) {
    return (uint32_t)__cvta_generic_to_shared(p);
}

__device__ __forceinline__ void mma_tf32(float* d, const uint32_t* a, const uint32_t* b) {
    asm volatile(
        "mma.sync.aligned.m16n8k8.row.col.f32.tf32.tf32.f32 "
        "{%0,%1,%2,%3}, {%4,%5,%6,%7}, {%8,%9}, {%0,%1,%2,%3};"
        : "+f"(d[0]), "+f"(d[1]), "+f"(d[2]), "+f"(d[3])
        : "r"(a[0]), "r"(a[1]), "r"(a[2]), "r"(a[3]), "r"(b[0]), "r"(b[1]));
}

// ================= tf32 tensor-core GEMM ======================================
// HOUT: write __half output (for value projection), else float. RELU optional.
template<bool RELU, bool HOUT>
__global__ __launch_bounds__(256)
void mmagemm(const float* __restrict__ A, const float* __restrict__ Bm,
             const float* __restrict__ bias, void* __restrict__ Cv,
             int M, int N, int K)
{
    extern __shared__ __align__(16) float sm[];
    float* As = sm;
    float* Bs = sm + 2 * ABUF;

    const int tid  = threadIdx.x;
    const int lane = tid & 31;
    const int wid  = tid >> 5;
    const int wm   = (wid & 1) * 64;
    const int wn   = (wid >> 1) * 32;
    const int mb   = blockIdx.y * 128;
    const int nb   = blockIdx.x * 128;
    const int g    = lane >> 2;
    const int t    = lane & 3;

    float acc[4][4][4];
    #pragma unroll
    for (int i = 0; i < 4; i++)
        #pragma unroll
        for (int j = 0; j < 4; j++)
            #pragma unroll
            for (int r = 0; r < 4; r++) acc[i][j][r] = 0.f;

    const int arow  = tid >> 3;
    const int acol  = (tid & 7) * 4;
    const int bk    = tid >> 5;
    const int bcol  = (tid & 31) * 4;

#define LOAD_CHUNK(buf, kt)                                                        \
    {                                                                              \
        _Pragma("unroll")                                                          \
        for (int i = 0; i < 4; i++) {                                              \
            int row = arow + i * 32;                                               \
            const float* gp = A + (size_t)(mb + row) * K + (kt) + acol;            \
            uint32_t sa = smem_u32(As + (buf) * ABUF + row * PA + acol);           \
            int zf = (mb + row < M) ? 16 : 0;                                      \
            asm volatile("cp.async.cg.shared.global [%0], [%1], 16, %2;"           \
                         :: "r"(sa), "l"(gp), "r"(zf));                            \
        }                                                                          \
        _Pragma("unroll")                                                          \
        for (int i = 0; i < 4; i++) {                                              \
            int k = bk + i * 8;                                                    \
            const float* gp = Bm + (size_t)((kt) + k) * N + nb + bcol;             \
            uint32_t sa = smem_u32(Bs + (buf) * BBUF + k * PB + bcol);             \
            asm volatile("cp.async.cg.shared.global [%0], [%1], 16;"               \
                         :: "r"(sa), "l"(gp));                                     \
        }                                                                          \
        asm volatile("cp.async.commit_group;");                                    \
    }

    const int NIT = K >> 5;
    LOAD_CHUNK(0, 0);

    for (int it = 0; it < NIT; it++) {
        const int buf = it & 1;
        if (it + 1 < NIT) {
            LOAD_CHUNK(1 - buf, (it + 1) << 5);
            asm volatile("cp.async.wait_group 1;");
        } else {
            asm volatile("cp.async.wait_group 0;");
        }
        __syncthreads();

        const float* a_base = As + buf * ABUF;
        const float* b_base = Bs + buf * BBUF;
        #pragma unroll
        for (int k0 = 0; k0 < 32; k0 += 8) {
            uint32_t af[4][4];
            uint32_t bf[4][2];
            #pragma unroll
            for (int mt = 0; mt < 4; mt++) {
                const float* p = a_base + (wm + mt * 16 + g) * PA + k0 + t;
                af[mt][0] = __float_as_uint(p[0]);
                af[mt][1] = __float_as_uint(p[8 * PA]);
                af[mt][2] = __float_as_uint(p[4]);
                af[mt][3] = __float_as_uint(p[8 * PA + 4]);
            }
            #pragma unroll
            for (int nt = 0; nt < 4; nt++) {
                const float* p = b_base + (k0 + t) * PB + wn + nt * 8 + g;
                bf[nt][0] = __float_as_uint(p[0]);
                bf[nt][1] = __float_as_uint(p[4 * PB]);
            }
            #pragma unroll
            for (int mt = 0; mt < 4; mt++)
                #pragma unroll
                for (int nt = 0; nt < 4; nt++)
                    mma_tf32(acc[mt][nt], af[mt], bf[nt]);
        }
        __syncthreads();
    }
#undef LOAD_CHUNK

    #pragma unroll
    for (int mt = 0; mt < 4; mt++) {
        const int r0 = mb + wm + mt * 16 + g;
        const int r1 = r0 + 8;
        #pragma unroll
        for (int nt = 0; nt < 4; nt++) {
            const int c = nb + wn + nt * 8 + t * 2;
            const float b0 = __ldg(bias + c);
            const float b1 = __ldg(bias + c + 1);
            float v0 = acc[mt][nt][0] + b0;
            float v1 = acc[mt][nt][1] + b1;
            float v2 = acc[mt][nt][2] + b0;
            float v3 = acc[mt][nt][3] + b1;
            if (RELU) {
                v0 = fmaxf(v0, 0.f); v1 = fmaxf(v1, 0.f);
                v2 = fmaxf(v2, 0.f); v3 = fmaxf(v3, 0.f);
            }
            if (HOUT) {
                __half* Ch = (__half*)Cv;
                if (r0 < M) *(__half2*)(Ch + (size_t)r0 * N + c) = __floats2half2_rn(v0, v1);
                if (r1 < M) *(__half2*)(Ch + (size_t)r1 * N + c) = __floats2half2_rn(v2, v3);
            } else {
                float* Cf = (float*)Cv;
                if (r0 < M) *(float2*)(Cf + (size_t)r0 * N + c) = make_float2(v0, v1);
                if (r1 < M) *(float2*)(Cf + (size_t)r1 * N + c) = make_float2(v2, v3);
            }
        }
    }
}

// ---------------- elementwise add --------------------------------------------
__global__ void add_kernel(const float* __restrict__ a, const float* __restrict__ b,
                           float* __restrict__ o, int n4) {
    int i = blockIdx.x * blockDim.x + threadIdx.x;
    if (i < n4) {
        float4 x = ((const float4*)a)[i];
        float4 y = ((const float4*)b)[i];
        ((float4*)o)[i] = make_float4(x.x + y.x, x.y + y.y, x.z + y.z, x.w + y.w);
    }
}

// ---------------- deformable sampling (half value, branchless) ----------------
__global__ void sample_kernel(const __half* __restrict__ value,
                              const float* __restrict__ offs,
                              const float* __restrict__ logits,
                              float* __restrict__ out) {
    int gw = (blockIdx.x * blockDim.x + threadIdx.x) >> 5;
    if (gw >= MT * HH) return;
    const int lane = threadIdx.x & 31;
    const int h  = gw & 7;
    const int bs = gw >> 3;
    const int s  = bs % SS;
    const int rowb = bs - s;

    float refx, refy;
    {
        int lvlH, lvlW, idx;
        if (s < 6400)      { lvlH = 80; lvlW = 80; idx = s; }
        else if (s < 8000) { lvlH = 40; lvlW = 40; idx = s - 6400; }
        else if (s < 8400) { lvlH = 20; lvlW = 20; idx = s - 8000; }
        else               { lvlH = 10; lvlW = 10; idx = s - 8400; }
        refx = ((idx % lvlW) + 0.5f) / (float)lvlW;
        refy = ((idx / lvlW) + 0.5f) / (float)lvlH;
    }

    const float* lg = logits + (size_t)gw * 16;
    float w[16];
    float mx = -1e30f;
    #pragma unroll
    for (int i = 0; i < 16; i++) { w[i] = __ldg(lg + i); mx = fmaxf(mx, w[i]); }
    float sum = 0.f;
    #pragma unroll
    for (int i = 0; i < 16; i++) { w[i] = __expf(w[i] - mx); sum += w[i]; }
    const float inv = 1.0f / sum;

    const float* of = offs + (size_t)gw * 32;
    const int d0 = h * DD + lane * 2;
    float ax = 0.f, ay = 0.f;

    const int LH[4] = {80, 40, 20, 10};
    const int LW[4] = {80, 40, 20, 10};
    const int LS[4] = {0, 6400, 8000, 8400};

    #pragma unroll
    for (int l = 0; l < 4; l++) {
        const int Hh = LH[l], Ww = LW[l];
        const __half* vb = value + (size_t)(rowb + LS[l]) * CC + d0;
        #pragma unroll
        for (int p = 0; p < 4; p++) {
            float ox = __ldg(of + (l * 4 + p) * 2);
            float oy = __ldg(of + (l * 4 + p) * 2 + 1);
            float aw = w[l * 4 + p] * inv;
            float x = refx * (float)Ww + ox - 0.5f;
            float y = refy * (float)Hh + oy - 0.5f;
            float xf = floorf(x), yf = floorf(y);
            int x0 = (int)xf, y0 = (int)yf;
            float fx = x - xf, fy = y - yf;

            float mx0 = (x0 >= 0 && x0 < Ww)         ? 1.f : 0.f;
            float mx1 = (x0 + 1 >= 0 && x0 + 1 < Ww) ? 1.f : 0.f;
            float my0 = (y0 >= 0 && y0 < Hh)         ? 1.f : 0.f;
            float my1 = (y0 + 1 >= 0 && y0 + 1 < Hh) ? 1.f : 0.f;

            int xc0 = min(max(x0, 0), Ww - 1);
            int xc1 = min(max(x0 + 1, 0), Ww - 1);
            int yc0 = min(max(y0, 0), Hh - 1);
            int yc1 = min(max(y0 + 1, 0), Hh - 1);

            const __half2 h00 = *(const __half2*)(vb + (size_t)(yc0 * Ww + xc0) * CC);
            const __half2 h01 = *(const __half2*)(vb + (size_t)(yc0 * Ww + xc1) * CC);
            const __half2 h10 = *(const __half2*)(vb + (size_t)(yc1 * Ww + xc0) * CC);
            const __half2 h11 = *(const __half2*)(vb + (size_t)(yc1 * Ww + xc1) * CC);

            float w00 = (1.f - fx) * (1.f - fy) * aw * mx0 * my0;
            float w01 = fx * (1.f - fy) * aw * mx1 * my0;
            float w10 = (1.f - fx) * fy * aw * mx0 * my1;
            float w11 = fx * fy * aw * mx1 * my1;

            float2 f00 = __half22float2(h00);
            float2 f01 = __half22float2(h01);
            float2 f10 = __half22float2(h10);
            float2 f11 = __half22float2(h11);

            ax += w00 * f00.x + w01 * f01.x + w10 * f10.x + w11 * f11.x;
            ay += w00 * f00.y + w01 * f01.y + w10 * f10.y + w11 * f11.y;
        }
    }
    *(float2*)(out + (size_t)bs * CC + d0) = make_float2(ax, ay);
}

// ---------------- fused residual + LayerNorm ---------------------------------
__global__ void ln_residual(const float* __restrict__ a, const float* __restrict__ r,
                            const float* __restrict__ g, const float* __restrict__ bta,
                            float* __restrict__ out) {
    const int row = blockIdx.x;
    const int t = threadIdx.x;
    const float4 va = ((const float4*)(a + (size_t)row * CC))[t];
    const float4 vr = ((const float4*)(r + (size_t)row * CC))[t];
    float x0 = va.x + vr.x, x1 = va.y + vr.y, x2 = va.z + vr.z, x3 = va.w + vr.w;

    float sum = x0 + x1 + x2 + x3;
    float sq  = x0 * x0 + x1 * x1 + x2 * x2 + x3 * x3;
    #pragma unroll
    for (int o = 16; o; o >>= 1) {
        sum += __shfl_xor_sync(0xffffffffu, sum, o);
        sq  += __shfl_xor_sync(0xffffffffu, sq,  o);
    }
    __shared__ float sh[8];
    const int wid = t >> 5, lane = t & 31;
    if (lane == 0) { sh[wid] = sum; sh[wid + 4] = sq; }
    __syncthreads();
    sum = sh[0] + sh[1] + sh[2] + sh[3];
    sq  = sh[4] + sh[5] + sh[6] + sh[7];

    const float mean = sum * (1.0f / CC);
    const float var  = sq * (1.0f / CC) - mean * mean;
    const float istd = rsqrtf(var + 1e-5f);

    const float4 vg = ((const float4*)g)[t];
    const float4 vb = ((const float4*)bta)[t];
    float4 o4;
    o4.x = (x0 - mean) * istd * vg.x + vb.x;
    o4.y = (x1 - mean) * istd * vg.y + vb.y;
    o4.z = (x2 - mean) * istd * vg.z + vb.z;
    o4.w = (x3 - mean) * istd * vg.w + vb.w;
    ((float4*)(out + (size_t)row * CC))[t] = o4;
}

// ---------------- launch ------------------------------------------------------
static void* symv(const void* s) {
    void* p = nullptr;
    cudaGetSymbolAddress(&p, s);
    return p;
}

extern "C" void kernel_launch(void* const* d_in, const int* in_sizes, int n_in,
                              void* d_out, int out_size) {
    const float* src    = (const float*)d_in[0];
    const float* pos    = (const float*)d_in[1];
    const float* w_off  = (const float*)d_in[2];
    const float* b_off  = (const float*)d_in[3];
    const float* w_attn = (const float*)d_in[4];
    const float* b_attn = (const float*)d_in[5];
    const float* w_val  = (const float*)d_in[6];
    const float* b_val  = (const float*)d_in[7];
    const float* w_out  = (const float*)d_in[8];
    const float* b_out  = (const float*)d_in[9];
    const float* ln1_g  = (const float*)d_in[10];
    const float* ln1_b  = (const float*)d_in[11];
    const float* w1     = (const float*)d_in[12];
    const float* b1     = (const float*)d_in[13];
    const float* w2     = (const float*)d_in[14];
    const float* b2     = (const float*)d_in[15];
    const float* ln2_g  = (const float*)d_in[16];
    const float* ln2_b  = (const float*)d_in[17];
    float* out = (float*)d_out;

    float*  q    = (float*)symv(g_q);
    __half* valh = (__half*)symv(g_valh);
    float*  off  = (float*)symv(g_off);
    float*  lgt  = (float*)symv(g_lgt);
    float*  smp  = (float*)symv(g_smp);
    float*  tmp  = (float*)symv(g_tmp);
    float*  x    = (float*)symv(g_x);
    float*  hid  = (float*)symv(g_hid);

    const int SMEM_SZ = SMEM_FLOATS * 4;
    cudaFuncSetAttribute(mmagemm<false,false>, cudaFuncAttributeMaxDynamicSharedMemorySize, SMEM_SZ);
    cudaFuncSetAttribute(mmagemm<true,false>,  cudaFuncAttributeMaxDynamicSharedMemorySize, SMEM_SZ);
    cudaFuncSetAttribute(mmagemm<false,true>,  cudaFuncAttributeMaxDynamicSharedMemorySize, SMEM_SZ);

    const int mblocks = (MT + 127) / 128;

    // 1. q = src + pos
    {
        int n4 = MT * CC / 4;
        add_kernel<<<(n4 + 255) / 256, 256>>>(src, pos, q, n4);
    }
    // 2. value = src @ w_val + b_val  -> fp16
    mmagemm<false,true><<<dim3(CC / 128, mblocks), 256, SMEM_SZ>>>(src, w_val, b_val, valh, MT, CC, CC);
    // 3. offsets = q @ w_off + b_off
    mmagemm<false,false><<<dim3(256 / 128, mblocks), 256, SMEM_SZ>>>(q, w_off, b_off, off, MT, 256, CC);
    // 4. logits = q @ w_attn + b_attn
    mmagemm<false,false><<<dim3(1, mblocks), 256, SMEM_SZ>>>(q, w_attn, b_attn, lgt, MT, 128, CC);
    // 5. deformable sampling
    {
        int warps = MT * HH;
        int blocks = (warps * 32 + 255) / 256;
        sample_kernel<<<blocks, 256>>>(valh, off, lgt, smp);
    }
    // 6. attn_out = smp @ w_out + b_out
    mmagemm<false,false><<<dim3(CC / 128, mblocks), 256, SMEM_SZ>>>(smp, w_out, b_out, tmp, MT, CC, CC);
    // 7. x = LN(src + attn_out)
    ln_residual<<<MT, 128>>>(src, tmp, ln1_g, ln1_b, x);
    // 8. hid = relu(x @ w1 + b1)
    mmagemm<true,false><<<dim3(DFFN / 128, mblocks), 256, SMEM_SZ>>>(x, w1, b1, hid, MT, DFFN, CC);
    // 9. ffn = hid @ w2 + b2
    mmagemm<false,false><<<dim3(CC / 128, mblocks), 256, SMEM_SZ>>>(hid, w2, b2, tmp, MT, CC, DFFN);
    // 10. out = LN(x + ffn)
    ln_residual<<<MT, 128>>>(x, tmp, ln2_g, ln2_b, out);
}

// round 5
// speedup vs baseline: 1.2420x; 1.2420x over previous
#include <cuda_runtime.h>
#include <math.h>
#include <stdint.h>

#define BB 2
#define SS 8500
#define CC 512
#define HH 8
#define DD 64
#define DFFN 1024
#define MT (BB*SS)   // 17000

#define PA 36
#define PB 136
#define ABUF (128*PA)
#define BBUF (32*PB)
#define SMEM_FLOATS (2*ABUF + 2*BBUF)

// ---------------- scratch ------------------------------------------------------
__device__ float g_q   [MT*CC];
__device__ float g_val [MT*CC];
__device__ float g_off [MT*256];
__device__ float g_lgt [MT*128];
__device__ float g_smp [MT*CC];
__device__ float g_tmp [MT*CC];
__device__ float g_x   [MT*CC];
__device__ float g_hid [MT*DFFN];

__device__ __forceinline__ uint32_t smem_u32(const void* p) {
    return (uint32_t)__cvta_generic_to_shared(p);
}

__device__ __forceinline__ void mma_tf32(float* d, const uint32_t* a, const uint32_t* b) {
    asm volatile(
        "mma.sync.aligned.m16n8k8.row.col.f32.tf32.tf32.f32 "
        "{%0,%1,%2,%3}, {%4,%5,%6,%7}, {%8,%9}, {%0,%1,%2,%3};"
        : "+f"(d[0]), "+f"(d[1]), "+f"(d[2]), "+f"(d[3])
        : "r"(a[0]), "r"(a[1]), "r"(a[2]), "r"(a[3]), "r"(b[0]), "r"(b[1]));
}

// ================= tf32 tensor-core GEMM ======================================
template<bool RELU>
__global__ __launch_bounds__(256, 2)
void mmagemm(const float* __restrict__ A, const float* __restrict__ Bm,
             const float* __restrict__ bias, float* __restrict__ C,
             int M, int N, int K)
{
    extern __shared__ __align__(16) float sm[];
    float* As = sm;
    float* Bs = sm + 2 * ABUF;

    const int tid  = threadIdx.x;
    const int lane = tid & 31;
    const int wid  = tid >> 5;
    const int wm   = (wid & 1) * 64;
    const int wn   = (wid >> 1) * 32;
    const int mb   = blockIdx.y * 128;
    const int nb   = blockIdx.x * 128;
    const int g    = lane >> 2;
    const int t    = lane & 3;

    float acc[4][4][4];
    #pragma unroll
    for (int i = 0; i < 4; i++)
        #pragma unroll
        for (int j = 0; j < 4; j++)
            #pragma unroll
            for (int r = 0; r < 4; r++) acc[i][j][r] = 0.f;

    const int arow  = tid >> 3;
    const int acol  = (tid & 7) * 4;
    const int bk    = tid >> 5;
    const int bcol  = (tid & 31) * 4;

#define LOAD_CHUNK(buf, kt)                                                        \
    {                                                                              \
        _Pragma("unroll")                                                          \
        for (int i = 0; i < 4; i++) {                                              \
            int row = arow + i * 32;                                               \
            const float* gp = A + (size_t)(mb + row) * K + (kt) + acol;            \
            uint32_t sa = smem_u32(As + (buf) * ABUF + row * PA + acol);           \
            int zf = (mb + row < M) ? 16 : 0;                                      \
            asm volatile("cp.async.cg.shared.global [%0], [%1], 16, %2;"           \
                         :: "r"(sa), "l"(gp), "r"(zf));                            \
        }                                                                          \
        _Pragma("unroll")                                                          \
        for (int i = 0; i < 4; i++) {                                              \
            int k = bk + i * 8;                                                    \
            const float* gp = Bm + (size_t)((kt) + k) * N + nb + bcol;             \
            uint32_t sa = smem_u32(Bs + (buf) * BBUF + k * PB + bcol);             \
            asm volatile("cp.async.cg.shared.global [%0], [%1], 16;"               \
                         :: "r"(sa), "l"(gp));                                     \
        }                                                                          \
        asm volatile("cp.async.commit_group;");                                    \
    }

    const int NIT = K >> 5;
    LOAD_CHUNK(0, 0);

    for (int it = 0; it < NIT; it++) {
        const int buf = it & 1;
        if (it + 1 < NIT) {
            LOAD_CHUNK(1 - buf, (it + 1) << 5);
            asm volatile("cp.async.wait_group 1;");
        } else {
            asm volatile("cp.async.wait_group 0;");
        }
        __syncthreads();

        const float* a_base = As + buf * ABUF;
        const float* b_base = Bs + buf * BBUF;
        #pragma unroll
        for (int k0 = 0; k0 < 32; k0 += 8) {
            uint32_t af[4][4];
            uint32_t bf[4][2];
            #pragma unroll
            for (int mt = 0; mt < 4; mt++) {
                const float* p = a_base + (wm + mt * 16 + g) * PA + k0 + t;
                af[mt][0] = __float_as_uint(p[0]);
                af[mt][1] = __float_as_uint(p[8 * PA]);
                af[mt][2] = __float_as_uint(p[4]);
                af[mt][3] = __float_as_uint(p[8 * PA + 4]);
            }
            #pragma unroll
            for (int nt = 0; nt < 4; nt++) {
                const float* p = b_base + (k0 + t) * PB + wn + nt * 8 + g;
                bf[nt][0] = __float_as_uint(p[0]);
                bf[nt][1] = __float_as_uint(p[4 * PB]);
            }
            #pragma unroll
            for (int mt = 0; mt < 4; mt++)
                #pragma unroll
                for (int nt = 0; nt < 4; nt++)
                    mma_tf32(acc[mt][nt], af[mt], bf[nt]);
        }
        __syncthreads();
    }
#undef LOAD_CHUNK

    #pragma unroll
    for (int mt = 0; mt < 4; mt++) {
        const int r0 = mb + wm + mt * 16 + g;
        const int r1 = r0 + 8;
        #pragma unroll
        for (int nt = 0; nt < 4; nt++) {
            const int c = nb + wn + nt * 8 + t * 2;
            const float b0 = __ldg(bias + c);
            const float b1 = __ldg(bias + c + 1);
            float v0 = acc[mt][nt][0] + b0;
            float v1 = acc[mt][nt][1] + b1;
            float v2 = acc[mt][nt][2] + b0;
            float v3 = acc[mt][nt][3] + b1;
            if (RELU) {
                v0 = fmaxf(v0, 0.f); v1 = fmaxf(v1, 0.f);
                v2 = fmaxf(v2, 0.f); v3 = fmaxf(v3, 0.f);
            }
            if (r0 < M) *(float2*)(C + (size_t)r0 * N + c) = make_float2(v0, v1);
            if (r1 < M) *(float2*)(C + (size_t)r1 * N + c) = make_float2(v2, v3);
        }
    }
}

// ---------------- elementwise add --------------------------------------------
__global__ void add_kernel(const float* __restrict__ a, const float* __restrict__ b,
                           float* __restrict__ o, int n4) {
    int i = blockIdx.x * blockDim.x + threadIdx.x;
    if (i < n4) {
        float4 x = ((const float4*)a)[i];
        float4 y = ((const float4*)b)[i];
        ((float4*)o)[i] = make_float4(x.x + y.x, x.y + y.y, x.z + y.z, x.w + y.w);
    }
}

// ---------------- deformable sampling: minimal-issue version ------------------
// one warp per (bs, h); lane covers 2 of 64 channels (float2 = 8B, coalesced).
// Per point: 1 base address; other corners at compile-time immediate offsets.
// Out-of-bounds corners: predicated-off loads leave zero -> no weight masking.
__global__ void sample_kernel(const float* __restrict__ value,
                              const float* __restrict__ offs,
                              const float* __restrict__ logits,
                              float* __restrict__ out) {
    int gw = (blockIdx.x * blockDim.x + threadIdx.x) >> 5;
    if (gw >= MT * HH) return;
    const int lane = threadIdx.x & 31;
    const int h  = gw & 7;
    const int bs = gw >> 3;
    const int s  = bs % SS;
    const int rowb = bs - s;

    // query reference point (normalized), from the query's own level
    float refx, refy;
    {
        int lvlH, lvlW, idx;
        if (s < 6400)      { lvlH = 80; lvlW = 80; idx = s; }
        else if (s < 8000) { lvlH = 40; lvlW = 40; idx = s - 6400; }
        else if (s < 8400) { lvlH = 20; lvlW = 20; idx = s - 8000; }
        else               { lvlH = 10; lvlW = 10; idx = s - 8400; }
        refx = ((idx % lvlW) + 0.5f) / (float)lvlW;
        refy = ((idx / lvlW) + 0.5f) / (float)lvlH;
    }

    // softmax over 16 logits (vectorized preload)
    float w[16];
    {
        const float4* lg4 = (const float4*)(logits + (size_t)gw * 16);
        float4 a0 = __ldg(lg4 + 0), a1 = __ldg(lg4 + 1);
        float4 a2 = __ldg(lg4 + 2), a3 = __ldg(lg4 + 3);
        w[0]=a0.x; w[1]=a0.y; w[2]=a0.z; w[3]=a0.w;
        w[4]=a1.x; w[5]=a1.y; w[6]=a1.z; w[7]=a1.w;
        w[8]=a2.x; w[9]=a2.y; w[10]=a2.z; w[11]=a2.w;
        w[12]=a3.x; w[13]=a3.y; w[14]=a3.z; w[15]=a3.w;
        float mx = w[0];
        #pragma unroll
        for (int i = 1; i < 16; i++) mx = fmaxf(mx, w[i]);
        float sum = 0.f;
        #pragma unroll
        for (int i = 0; i < 16; i++) { w[i] = __expf(w[i] - mx); sum += w[i]; }
        const float inv = 1.0f / sum;
        #pragma unroll
        for (int i = 0; i < 16; i++) w[i] *= inv;
    }

    // offsets preload: 32 floats = 8 float4 (points 2i, 2i+1)
    float4 o4[8];
    {
        const float4* op = (const float4*)(offs + (size_t)gw * 32);
        #pragma unroll
        for (int i = 0; i < 8; i++) o4[i] = __ldg(op + i);
    }

    const int d0 = h * DD + lane * 2;
    float ax = 0.f, ay = 0.f;

    const int   LW[4] = {80, 40, 20, 10};
    const int   LH[4] = {80, 40, 20, 10};
    const int   LS[4] = {0, 6400, 8000, 8400};

    #pragma unroll
    for (int l = 0; l < 4; l++) {
        const int Wl = LW[l], Hl = LH[l];
        const float rxm = refx * (float)Wl - 0.5f;
        const float rym = refy * (float)Hl - 0.5f;
        const char* vb = (const char*)(value + (size_t)(rowb + LS[l]) * CC + d0);
        const int ROWB = Wl * (CC * 4);             // bytes per spatial row
        #pragma unroll
        for (int p = 0; p < 4; p++) {
            const int pi = l * 4 + p;
            const float ox = (pi & 1) ? o4[pi >> 1].z : o4[pi >> 1].x;
            const float oy = (pi & 1) ? o4[pi >> 1].w : o4[pi >> 1].y;
            const float aw = w[pi];

            const float x = rxm + ox;
            const float y = rym + oy;
            const int x0 = __float2int_rd(x);
            const int y0 = __float2int_rd(y);
            const float fx = x - (float)x0;
            const float fy = y - (float)y0;

            const bool px0 = (unsigned)x0 < (unsigned)Wl;
            const bool px1 = (unsigned)(x0 + 1) < (unsigned)Wl;
            const bool py0 = (unsigned)y0 < (unsigned)Hl;
            const bool py1 = (unsigned)(y0 + 1) < (unsigned)Hl;

            const char* pc = vb + ((size_t)(y0 * Wl + x0) * (CC * 4));
            float2 v00 = make_float2(0.f, 0.f);
            float2 v01 = v00, v10 = v00, v11 = v00;
            if (px0 & py0) v00 = *(const float2*)(pc);
            if (px1 & py0) v01 = *(const float2*)(pc + CC * 4);
            if (px0 & py1) v10 = *(const float2*)(pc + ROWB);
            if (px1 & py1) v11 = *(const float2*)(pc + ROWB + CC * 4);

            const float gx0 = 1.f - fx;
            const float wy0 = (1.f - fy) * aw;
            const float wy1 = fy * aw;
            const float w00 = gx0 * wy0, w01 = fx * wy0;
            const float w10 = gx0 * wy1, w11 = fx * wy1;

            ax += w00 * v00.x + w01 * v01.x + w10 * v10.x + w11 * v11.x;
            ay += w00 * v00.y + w01 * v01.y + w10 * v10.y + w11 * v11.y;
        }
    }
    *(float2*)(out + (size_t)bs * CC + d0) = make_float2(ax, ay);
}

// ---------------- fused residual + LayerNorm ---------------------------------
__global__ void ln_residual(const float* __restrict__ a, const float* __restrict__ r,
                            const float* __restrict__ g, const float* __restrict__ bta,
                            float* __restrict__ out) {
    const int row = blockIdx.x;
    const int t = threadIdx.x;
    const float4 va = ((const float4*)(a + (size_t)row * CC))[t];
    const float4 vr = ((const float4*)(r + (size_t)row * CC))[t];
    float x0 = va.x + vr.x, x1 = va.y + vr.y, x2 = va.z + vr.z, x3 = va.w + vr.w;

    float sum = x0 + x1 + x2 + x3;
    float sq  = x0 * x0 + x1 * x1 + x2 * x2 + x3 * x3;
    #pragma unroll
    for (int o = 16; o; o >>= 1) {
        sum += __shfl_xor_sync(0xffffffffu, sum, o);
        sq  += __shfl_xor_sync(0xffffffffu, sq,  o);
    }
    __shared__ float sh[8];
    const int wid = t >> 5, lane = t & 31;
    if (lane == 0) { sh[wid] = sum; sh[wid + 4] = sq; }
    __syncthreads();
    sum = sh[0] + sh[1] + sh[2] + sh[3];
    sq  = sh[4] + sh[5] + sh[6] + sh[7];

    const float mean = sum * (1.0f / CC);
    const float var  = sq * (1.0f / CC) - mean * mean;
    const float istd = rsqrtf(var + 1e-5f);

    const float4 vg = ((const float4*)g)[t];
    const float4 vb = ((const float4*)bta)[t];
    float4 o4;
    o4.x = (x0 - mean) * istd * vg.x + vb.x;
    o4.y = (x1 - mean) * istd * vg.y + vb.y;
    o4.z = (x2 - mean) * istd * vg.z + vb.z;
    o4.w = (x3 - mean) * istd * vg.w + vb.w;
    ((float4*)(out + (size_t)row * CC))[t] = o4;
}

// ---------------- launch ------------------------------------------------------
static void* symv(const void* s) {
    void* p = nullptr;
    cudaGetSymbolAddress(&p, s);
    return p;
}

extern "C" void kernel_launch(void* const* d_in, const int* in_sizes, int n_in,
                              void* d_out, int out_size) {
    const float* src    = (const float*)d_in[0];
    const float* pos    = (const float*)d_in[1];
    const float* w_off  = (const float*)d_in[2];
    const float* b_off  = (const float*)d_in[3];
    const float* w_attn = (const float*)d_in[4];
    const float* b_attn = (const float*)d_in[5];
    const float* w_val  = (const float*)d_in[6];
    const float* b_val  = (const float*)d_in[7];
    const float* w_out  = (const float*)d_in[8];
    const float* b_out  = (const float*)d_in[9];
    const float* ln1_g  = (const float*)d_in[10];
    const float* ln1_b  = (const float*)d_in[11];
    const float* w1     = (const float*)d_in[12];
    const float* b1     = (const float*)d_in[13];
    const float* w2     = (const float*)d_in[14];
    const float* b2     = (const float*)d_in[15];
    const float* ln2_g  = (const float*)d_in[16];
    const float* ln2_b  = (const float*)d_in[17];
    float* out = (float*)d_out;

    float* q    = (float*)symv(g_q);
    float* val  = (float*)symv(g_val);
    float* off  = (float*)symv(g_off);
    float* lgt  = (float*)symv(g_lgt);
    float* smp  = (float*)symv(g_smp);
    float* tmp  = (float*)symv(g_tmp);
    float* x    = (float*)symv(g_x);
    float* hid  = (float*)symv(g_hid);

    const int SMEM_SZ = SMEM_FLOATS * 4;
    cudaFuncSetAttribute(mmagemm<false>, cudaFuncAttributeMaxDynamicSharedMemorySize, SMEM_SZ);
    cudaFuncSetAttribute(mmagemm<true>,  cudaFuncAttributeMaxDynamicSharedMemorySize, SMEM_SZ);

    const int mblocks = (MT + 127) / 128;

    // 1. q = src + pos
    {
        int n4 = MT * CC / 4;
        add_kernel<<<(n4 + 255) / 256, 256>>>(src, pos, q, n4);
    }
    // 2. value = src @ w_val + b_val
    mmagemm<false><<<dim3(CC / 128, mblocks), 256, SMEM_SZ>>>(src, w_val, b_val, val, MT, CC, CC);
    // 3. offsets = q @ w_off + b_off
    mmagemm<false><<<dim3(256 / 128, mblocks), 256, SMEM_SZ>>>(q, w_off, b_off, off, MT, 256, CC);
    // 4. logits = q @ w_attn + b_attn
    mmagemm<false><<<dim3(1, mblocks), 256, SMEM_SZ>>>(q, w_attn, b_attn, lgt, MT, 128, CC);
    // 5. deformable sampling
    {
        int warps = MT * HH;
        int blocks = (warps * 32 + 255) / 256;
        sample_kernel<<<blocks, 256>>>(val, off, lgt, smp);
    }
    // 6. attn_out = smp @ w_out + b_out
    mmagemm<false><<<dim3(CC / 128, mblocks), 256, SMEM_SZ>>>(smp, w_out, b_out, tmp, MT, CC, CC);
    // 7. x = LN(src + attn_out)
    ln_residual<<<MT, 128>>>(src, tmp, ln1_g, ln1_b, x);
    // 8. hid = relu(x @ w1 + b1)
    mmagemm<true><<<dim3(DFFN / 128, mblocks), 256, SMEM_SZ>>>(x, w1, b1, hid, MT, DFFN, CC);
    // 9. ffn = hid @ w2 + b2
    mmagemm<false><<<dim3(CC / 128, mblocks), 256, SMEM_SZ>>>(hid, w2, b2, tmp, MT, CC, DFFN);
    // 10. out = LN(x + ffn)
    ln_residual<<<MT, 128>>>(x, tmp, ln2_g, ln2_b, out);
}

// round 6
// speedup vs baseline: 1.3798x; 1.1109x over previous
#include <cuda_runtime.h>
#include <math.h>
#include <stdint.h>

#define BB 2
#define SS 8500
#define CC 512
#define HH 8
#define DD 64
#define DFFN 1024
#define MT (BB*SS)   // 17000
#define NPK 384      // packed off(256)+attn(128)

#define PA 36
#define PB 136
#define ABUF (128*PA)
#define BBUF (32*PB)
#define SMEM_FLOATS (2*ABUF + 2*BBUF)

// ---------------- scratch ------------------------------------------------------
__device__ float g_q    [MT*CC];
__device__ float g_val  [MT*CC];
__device__ float g_ol   [MT*NPK];   // [bs][ off(256) | lgt(128) ]
__device__ float g_smp  [MT*CC];
__device__ float g_tmp  [MT*CC];
__device__ float g_x    [MT*CC];
__device__ float g_hid  [MT*DFFN];
__device__ float g_wp   [CC*NPK];   // packed weights
__device__ float g_bp   [NPK];      // packed bias

__device__ __forceinline__ uint32_t smem_u32(const void* p) {
    return (uint32_t)__cvta_generic_to_shared(p);
}

__device__ __forceinline__ void mma_tf32(float* d, const uint32_t* a, const uint32_t* b) {
    asm volatile(
        "mma.sync.aligned.m16n8k8.row.col.f32.tf32.tf32.f32 "
        "{%0,%1,%2,%3}, {%4,%5,%6,%7}, {%8,%9}, {%0,%1,%2,%3};"
        : "+f"(d[0]), "+f"(d[1]), "+f"(d[2]), "+f"(d[3])
        : "r"(a[0]), "r"(a[1]), "r"(a[2]), "r"(a[3]), "r"(b[0]), "r"(b[1]));
}

// ---------------- pack w_off|w_attn -------------------------------------------
__global__ void pack_weights(const float* __restrict__ w_off, const float* __restrict__ w_attn,
                             const float* __restrict__ b_off, const float* __restrict__ b_attn,
                             float* __restrict__ wp, float* __restrict__ bp) {
    int i = blockIdx.x * blockDim.x + threadIdx.x;
    if (i < CC * NPK) {
        int r = i / NPK, c = i % NPK;
        wp[i] = (c < 256) ? w_off[r * 256 + c] : w_attn[r * 128 + (c - 256)];
    }
    if (i < NPK) bp[i] = (i < 256) ? b_off[i] : b_attn[i - 256];
}

// ================= tf32 tensor-core GEMM ======================================
template<bool RELU>
__global__ __launch_bounds__(256, 2)
void mmagemm(const float* __restrict__ A, const float* __restrict__ Bm,
             const float* __restrict__ bias, float* __restrict__ C,
             int M, int N, int K)
{
    extern __shared__ __align__(16) float sm[];
    float* As = sm;
    float* Bs = sm + 2 * ABUF;

    const int tid  = threadIdx.x;
    const int lane = tid & 31;
    const int wid  = tid >> 5;
    const int wm   = (wid & 1) * 64;
    const int wn   = (wid >> 1) * 32;
    const int mb   = blockIdx.y * 128;
    const int nb   = blockIdx.x * 128;
    const int g    = lane >> 2;
    const int t    = lane & 3;

    float acc[4][4][4];
    #pragma unroll
    for (int i = 0; i < 4; i++)
        #pragma unroll
        for (int j = 0; j < 4; j++)
            #pragma unroll
            for (int r = 0; r < 4; r++) acc[i][j][r] = 0.f;

    const int arow  = tid >> 3;
    const int acol  = (tid & 7) * 4;
    const int bk    = tid >> 5;
    const int bcol  = (tid & 31) * 4;

#define LOAD_CHUNK(buf, kt)                                                        \
    {                                                                              \
        _Pragma("unroll")                                                          \
        for (int i = 0; i < 4; i++) {                                              \
            int row = arow + i * 32;                                               \
            const float* gp = A + (size_t)(mb + row) * K + (kt) + acol;            \
            uint32_t sa = smem_u32(As + (buf) * ABUF + row * PA + acol);           \
            int zf = (mb + row < M) ? 16 : 0;                                      \
            asm volatile("cp.async.cg.shared.global [%0], [%1], 16, %2;"           \
                         :: "r"(sa), "l"(gp), "r"(zf));                            \
        }                                                                          \
        _Pragma("unroll")                                                          \
        for (int i = 0; i < 4; i++) {                                              \
            int k = bk + i * 8;                                                    \
            const float* gp = Bm + (size_t)((kt) + k) * N + nb + bcol;             \
            uint32_t sa = smem_u32(Bs + (buf) * BBUF + k * PB + bcol);             \
            asm volatile("cp.async.cg.shared.global [%0], [%1], 16;"               \
                         :: "r"(sa), "l"(gp));                                     \
        }                                                                          \
        asm volatile("cp.async.commit_group;");                                    \
    }

    const int NIT = K >> 5;
    LOAD_CHUNK(0, 0);

    for (int it = 0; it < NIT; it++) {
        const int buf = it & 1;
        if (it + 1 < NIT) {
            LOAD_CHUNK(1 - buf, (it + 1) << 5);
            asm volatile("cp.async.wait_group 1;");
        } else {
            asm volatile("cp.async.wait_group 0;");
        }
        __syncthreads();

        const float* a_base = As + buf * ABUF;
        const float* b_base = Bs + buf * BBUF;
        #pragma unroll
        for (int k0 = 0; k0 < 32; k0 += 8) {
            uint32_t af[4][4];
            uint32_t bf[4][2];
            #pragma unroll
            for (int mt = 0; mt < 4; mt++) {
                const float* p = a_base + (wm + mt * 16 + g) * PA + k0 + t;
                af[mt][0] = __float_as_uint(p[0]);
                af[mt][1] = __float_as_uint(p[8 * PA]);
                af[mt][2] = __float_as_uint(p[4]);
                af[mt][3] = __float_as_uint(p[8 * PA + 4]);
            }
            #pragma unroll
            for (int nt = 0; nt < 4; nt++) {
                const float* p = b_base + (k0 + t) * PB + wn + nt * 8 + g;
                bf[nt][0] = __float_as_uint(p[0]);
                bf[nt][1] = __float_as_uint(p[4 * PB]);
            }
            #pragma unroll
            for (int mt = 0; mt < 4; mt++)
                #pragma unroll
                for (int nt = 0; nt < 4; nt++)
                    mma_tf32(acc[mt][nt], af[mt], bf[nt]);
        }
        __syncthreads();
    }
#undef LOAD_CHUNK

    #pragma unroll
    for (int mt = 0; mt < 4; mt++) {
        const int r0 = mb + wm + mt * 16 + g;
        const int r1 = r0 + 8;
        #pragma unroll
        for (int nt = 0; nt < 4; nt++) {
            const int c = nb + wn + nt * 8 + t * 2;
            const float b0 = __ldg(bias + c);
            const float b1 = __ldg(bias + c + 1);
            float v0 = acc[mt][nt][0] + b0;
            float v1 = acc[mt][nt][1] + b1;
            float v2 = acc[mt][nt][2] + b0;
            float v3 = acc[mt][nt][3] + b1;
            if (RELU) {
                v0 = fmaxf(v0, 0.f); v1 = fmaxf(v1, 0.f);
                v2 = fmaxf(v2, 0.f); v3 = fmaxf(v3, 0.f);
            }
            if (r0 < M) *(float2*)(C + (size_t)r0 * N + c) = make_float2(v0, v1);
            if (r1 < M) *(float2*)(C + (size_t)r1 * N + c) = make_float2(v2, v3);
        }
    }
}

// ---------------- elementwise add --------------------------------------------
__global__ void add_kernel(const float* __restrict__ a, const float* __restrict__ b,
                           float* __restrict__ o, int n4) {
    int i = blockIdx.x * blockDim.x + threadIdx.x;
    if (i < n4) {
        float4 x = ((const float4*)a)[i];
        float4 y = ((const float4*)b)[i];
        ((float4*)o)[i] = make_float4(x.x + y.x, x.y + y.y, x.z + y.z, x.w + y.w);
    }
}

// ---------------- deformable sampling: 2 heads per warp, float4 per lane ------
// lane = hl*16 + li : hl selects head within pair, li covers 4 of 64 channels.
// Half-warps compute their own head's softmax/offsets in parallel.
__global__ void sample_kernel(const float* __restrict__ value,
                              const float* __restrict__ ol,     // packed off|lgt
                              float* __restrict__ out) {
    int gw = (blockIdx.x * blockDim.x + threadIdx.x) >> 5;
    if (gw >= MT * 4) return;
    const int lane = threadIdx.x & 31;
    const int hp = gw & 3;               // head pair
    const int bs = gw >> 2;
    const int s  = bs % SS;
    const int rowb = bs - s;
    const int hl = lane >> 4;            // head within pair
    const int li = lane & 15;            // channel quarter
    const int head = hp * 2 + hl;

    float refx, refy;
    {
        int lvlH, lvlW, idx;
        if (s < 6400)      { lvlH = 80; lvlW = 80; idx = s; }
        else if (s < 8000) { lvlH = 40; lvlW = 40; idx = s - 6400; }
        else if (s < 8400) { lvlH = 20; lvlW = 20; idx = s - 8000; }
        else               { lvlH = 10; lvlW = 10; idx = s - 8400; }
        refx = ((idx % lvlW) + 0.5f) / (float)lvlW;
        refy = ((idx / lvlW) + 0.5f) / (float)lvlH;
    }

    const float* base = ol + (size_t)bs * NPK;

    // softmax over this head's 16 logits
    float w[16];
    {
        const float4* lg4 = (const float4*)(base + 256 + head * 16);
        float4 a0 = __ldg(lg4 + 0), a1 = __ldg(lg4 + 1);
        float4 a2 = __ldg(lg4 + 2), a3 = __ldg(lg4 + 3);
        w[0]=a0.x; w[1]=a0.y; w[2]=a0.z; w[3]=a0.w;
        w[4]=a1.x; w[5]=a1.y; w[6]=a1.z; w[7]=a1.w;
        w[8]=a2.x; w[9]=a2.y; w[10]=a2.z; w[11]=a2.w;
        w[12]=a3.x; w[13]=a3.y; w[14]=a3.z; w[15]=a3.w;
        float mx = w[0];
        #pragma unroll
        for (int i = 1; i < 16; i++) mx = fmaxf(mx, w[i]);
        float sum = 0.f;
        #pragma unroll
        for (int i = 0; i < 16; i++) { w[i] = __expf(w[i] - mx); sum += w[i]; }
        const float inv = 1.0f / sum;
        #pragma unroll
        for (int i = 0; i < 16; i++) w[i] *= inv;
    }

    // this head's 32 offset floats
    float4 o4[8];
    {
        const float4* op = (const float4*)(base + head * 32);
        #pragma unroll
        for (int i = 0; i < 8; i++) o4[i] = __ldg(op + i);
    }

    const int d0 = head * DD + li * 4;
    float4 acc = make_float4(0.f, 0.f, 0.f, 0.f);

    const int LW[4] = {80, 40, 20, 10};
    const int LH[4] = {80, 40, 20, 10};
    const int LS[4] = {0, 6400, 8000, 8400};

    #pragma unroll
    for (int l = 0; l < 4; l++) {
        const int Wl = LW[l], Hl = LH[l];
        const float rxm = refx * (float)Wl - 0.5f;
        const float rym = refy * (float)Hl - 0.5f;
        const char* vb = (const char*)(value + (size_t)(rowb + LS[l]) * CC + d0);
        const int ROWB = Wl * (CC * 4);
        #pragma unroll
        for (int p = 0; p < 4; p++) {
            const int pi = l * 4 + p;
            const float ox = (pi & 1) ? o4[pi >> 1].z : o4[pi >> 1].x;
            const float oy = (pi & 1) ? o4[pi >> 1].w : o4[pi >> 1].y;
            const float aw = w[pi];

            const float x = rxm + ox;
            const float y = rym + oy;
            const int x0 = __float2int_rd(x);
            const int y0 = __float2int_rd(y);
            const float fx = x - (float)x0;
            const float fy = y - (float)y0;

            const bool px0 = (unsigned)x0 < (unsigned)Wl;
            const bool px1 = (unsigned)(x0 + 1) < (unsigned)Wl;
            const bool py0 = (unsigned)y0 < (unsigned)Hl;
            const bool py1 = (unsigned)(y0 + 1) < (unsigned)Hl;

            const char* pc = vb + ((size_t)(y0 * Wl + x0) * (CC * 4));
            float4 v00 = make_float4(0.f, 0.f, 0.f, 0.f);
            float4 v01 = v00, v10 = v00, v11 = v00;
            if (px0 & py0) v00 = *(const float4*)(pc);
            if (px1 & py0) v01 = *(const float4*)(pc + CC * 4);
            if (px0 & py1) v10 = *(const float4*)(pc + ROWB);
            if (px1 & py1) v11 = *(const float4*)(pc + ROWB + CC * 4);

            const float gx0 = 1.f - fx;
            const float wy0 = (1.f - fy) * aw;
            const float wy1 = fy * aw;
            const float w00 = gx0 * wy0, w01 = fx * wy0;
            const float w10 = gx0 * wy1, w11 = fx * wy1;

            acc.x += w00 * v00.x + w01 * v01.x + w10 * v10.x + w11 * v11.x;
            acc.y += w00 * v00.y + w01 * v01.y + w10 * v10.y + w11 * v11.y;
            acc.z += w00 * v00.z + w01 * v01.z + w10 * v10.z + w11 * v11.z;
            acc.w += w00 * v00.w + w01 * v01.w + w10 * v10.w + w11 * v11.w;
        }
    }
    *(float4*)(out + (size_t)bs * CC + d0) = acc;
}

// ---------------- fused residual + LayerNorm ---------------------------------
__global__ void ln_residual(const float* __restrict__ a, const float* __restrict__ r,
                            const float* __restrict__ g, const float* __restrict__ bta,
                            float* __restrict__ out) {
    const int row = blockIdx.x;
    const int t = threadIdx.x;
    const float4 va = ((const float4*)(a + (size_t)row * CC))[t];
    const float4 vr = ((const float4*)(r + (size_t)row * CC))[t];
    float x0 = va.x + vr.x, x1 = va.y + vr.y, x2 = va.z + vr.z, x3 = va.w + vr.w;

    float sum = x0 + x1 + x2 + x3;
    float sq  = x0 * x0 + x1 * x1 + x2 * x2 + x3 * x3;
    #pragma unroll
    for (int o = 16; o; o >>= 1) {
        sum += __shfl_xor_sync(0xffffffffu, sum, o);
        sq  += __shfl_xor_sync(0xffffffffu, sq,  o);
    }
    __shared__ float sh[8];
    const int wid = t >> 5, lane = t & 31;
    if (lane == 0) { sh[wid] = sum; sh[wid + 4] = sq; }
    __syncthreads();
    sum = sh[0] + sh[1] + sh[2] + sh[3];
    sq  = sh[4] + sh[5] + sh[6] + sh[7];

    const float mean = sum * (1.0f / CC);
    const float var  = sq * (1.0f / CC) - mean * mean;
    const float istd = rsqrtf(var + 1e-5f);

    const float4 vg = ((const float4*)g)[t];
    const float4 vb = ((const float4*)bta)[t];
    float4 o4;
    o4.x = (x0 - mean) * istd * vg.x + vb.x;
    o4.y = (x1 - mean) * istd * vg.y + vb.y;
    o4.z = (x2 - mean) * istd * vg.z + vb.z;
    o4.w = (x3 - mean) * istd * vg.w + vb.w;
    ((float4*)(out + (size_t)row * CC))[t] = o4;
}

// ---------------- launch ------------------------------------------------------
static void* symv(const void* s) {
    void* p = nullptr;
    cudaGetSymbolAddress(&p, s);
    return p;
}

extern "C" void kernel_launch(void* const* d_in, const int* in_sizes, int n_in,
                              void* d_out, int out_size) {
    const float* src    = (const float*)d_in[0];
    const float* pos    = (const float*)d_in[1];
    const float* w_off  = (const float*)d_in[2];
    const float* b_off  = (const float*)d_in[3];
    const float* w_attn = (const float*)d_in[4];
    const float* b_attn = (const float*)d_in[5];
    const float* w_val  = (const float*)d_in[6];
    const float* b_val  = (const float*)d_in[7];
    const float* w_out  = (const float*)d_in[8];
    const float* b_out  = (const float*)d_in[9];
    const float* ln1_g  = (const float*)d_in[10];
    const float* ln1_b  = (const float*)d_in[11];
    const float* w1     = (const float*)d_in[12];
    const float* b1     = (const float*)d_in[13];
    const float* w2     = (const float*)d_in[14];
    const float* b2     = (const float*)d_in[15];
    const float* ln2_g  = (const float*)d_in[16];
    const float* ln2_b  = (const float*)d_in[17];
    float* out = (float*)d_out;

    float* q    = (float*)symv(g_q);
    float* val  = (float*)symv(g_val);
    float* olb  = (float*)symv(g_ol);
    float* smp  = (float*)symv(g_smp);
    float* tmp  = (float*)symv(g_tmp);
    float* x    = (float*)symv(g_x);
    float* hid  = (float*)symv(g_hid);
    float* wp   = (float*)symv(g_wp);
    float* bp   = (float*)symv(g_bp);

    const int SMEM_SZ = SMEM_FLOATS * 4;
    cudaFuncSetAttribute(mmagemm<false>, cudaFuncAttributeMaxDynamicSharedMemorySize, SMEM_SZ);
    cudaFuncSetAttribute(mmagemm<true>,  cudaFuncAttributeMaxDynamicSharedMemorySize, SMEM_SZ);

    const int mblocks = (MT + 127) / 128;

    // 0. pack w_off|w_attn
    pack_weights<<<(CC * NPK + 255) / 256, 256>>>(w_off, w_attn, b_off, b_attn, wp, bp);
    // 1. q = src + pos
    {
        int n4 = MT * CC / 4;
        add_kernel<<<(n4 + 255) / 256, 256>>>(src, pos, q, n4);
    }
    // 2. value = src @ w_val + b_val
    mmagemm<false><<<dim3(CC / 128, mblocks), 256, SMEM_SZ>>>(src, w_val, b_val, val, MT, CC, CC);
    // 3. [offsets|logits] = q @ wp + bp
    mmagemm<false><<<dim3(NPK / 128, mblocks), 256, SMEM_SZ>>>(q, wp, bp, olb, MT, NPK, CC);
    // 4. deformable sampling (2 heads per warp)
    {
        int warps = MT * 4;
        int blocks = (warps * 32 + 255) / 256;
        sample_kernel<<<blocks, 256>>>(val, olb, smp);
    }
    // 5. attn_out = smp @ w_out + b_out
    mmagemm<false><<<dim3(CC / 128, mblocks), 256, SMEM_SZ>>>(smp, w_out, b_out, tmp, MT, CC, CC);
    // 6. x = LN(src + attn_out)
    ln_residual<<<MT, 128>>>(src, tmp, ln1_g, ln1_b, x);
    // 7. hid = relu(x @ w1 + b1)
    mmagemm<true><<<dim3(DFFN / 128, mblocks), 256, SMEM_SZ>>>(x, w1, b1, hid, MT, DFFN, CC);
    // 8. ffn = hid @ w2 + b2
    mmagemm<false><<<dim3(CC / 128, mblocks), 256, SMEM_SZ>>>(hid, w2, b2, tmp, MT, CC, DFFN);
    // 9. out = LN(x + ffn)
    ln_residual<<<MT, 128>>>(x, tmp, ln2_g, ln2_b, out);
}